// round 1
// baseline (speedup 1.0000x reference)
#include <cuda_runtime.h>
#include <cuda_fp16.h>
#include <cstdint>

#define B_  4
#define T_  400
#define U_  64
#define E_  320
#define INNER_ 512
#define VOCAB_ 1024
#define BT_ (B_*T_)      // 1600
#define BU_ (B_*U_)      // 256
#define BTU_ (B_*T_*U_)  // 102400

// Scratch (no allocations allowed -> __device__ globals)
__device__ float  g_Penc[BT_*INNER_];     // 3.1 MB
__device__ float  g_Pdec[BU_*INNER_];     // 0.5 MB
__device__ __half g_W2h[VOCAB_*INNER_];   // 1.0 MB

// ---------------------------------------------------------------------------
// Prologue: P = X @ W1_slice^T  (fp32, tiny: 0.6 GFLOP total)
// 8 rows per CTA; thread computes 2 output cols for all 8 rows.
// ---------------------------------------------------------------------------
__global__ __launch_bounds__(256) void proj_kernel(
    const float* __restrict__ enc, const float* __restrict__ dec,
    const float* __restrict__ W1)
{
    __shared__ float sx[8 * E_];
    int cb = blockIdx.x;
    bool isEnc = cb < (BT_ / 8);
    const float* X; float* P; int row0, coff;
    if (isEnc) { row0 = cb * 8;              X = enc; P = g_Penc; coff = 0;  }
    else       { row0 = (cb - BT_/8) * 8;    X = dec; P = g_Pdec; coff = E_; }

    int tid = threadIdx.x;
    for (int i = tid; i < 8 * E_; i += 256)
        sx[i] = X[(row0 + i / E_) * E_ + (i % E_)];
    __syncthreads();

    int i0 = tid, i1 = tid + 256;
    const float* w0p = W1 + i0 * (2 * E_) + coff;
    const float* w1p = W1 + i1 * (2 * E_) + coff;

    float acc[16];
    #pragma unroll
    for (int r = 0; r < 16; r++) acc[r] = 0.f;

    #pragma unroll 4
    for (int e = 0; e < E_; ++e) {
        float w0 = w0p[e], w1 = w1p[e];
        #pragma unroll
        for (int r = 0; r < 8; r++) {
            float xv = sx[r * E_ + e];
            acc[r*2+0] = fmaf(xv, w0, acc[r*2+0]);
            acc[r*2+1] = fmaf(xv, w1, acc[r*2+1]);
        }
    }
    #pragma unroll
    for (int r = 0; r < 8; r++) {
        P[(row0 + r) * INNER_ + i0] = acc[r*2+0];
        P[(row0 + r) * INNER_ + i1] = acc[r*2+1];
    }
}

// ---------------------------------------------------------------------------
// W2 fp32 -> fp16
// ---------------------------------------------------------------------------
__global__ __launch_bounds__(256) void w2_convert(const float* __restrict__ W2)
{
    int i = (blockIdx.x * 256 + threadIdx.x) * 2;
    float2 v = *(const float2*)(W2 + i);
    *(__half2*)(g_W2h + i) = __floats2half2_rn(v.x, v.y);
}

// ---------------------------------------------------------------------------
// Main fused kernel: h = tanh(Penc[bt] + Pdec[bu] + b1) computed ONCE into
// SMEM (fp16), then 4 vocab tiles of 256 via m16n8k16 HMMA, epilogue +b2.
// ---------------------------------------------------------------------------
#define HS_STRIDE 520   // 512 + 8 halves: 260 words == 4 mod 32 -> conflict-free frags
#define WS_STRIDE 72    // 64 + 8 halves:  36 words  == 4 mod 32 -> conflict-free frags
#define SMEM_BYTES ((128 * HS_STRIDE + 256 * WS_STRIDE) * (int)sizeof(__half))

__device__ __forceinline__ float tanh_fast(float x) {
    float y; asm("tanh.approx.f32 %0, %1;" : "=f"(y) : "f"(x)); return y;
}

__device__ __forceinline__ void mma16816(float* d, const uint32_t* a, const uint32_t* b) {
    asm volatile(
        "mma.sync.aligned.m16n8k16.row.col.f32.f16.f16.f32 "
        "{%0,%1,%2,%3}, {%4,%5,%6,%7}, {%8,%9}, {%0,%1,%2,%3};\n"
        : "+f"(d[0]), "+f"(d[1]), "+f"(d[2]), "+f"(d[3])
        : "r"(a[0]), "r"(a[1]), "r"(a[2]), "r"(a[3]), "r"(b[0]), "r"(b[1]));
}

__global__ __launch_bounds__(512, 1) void joint_kernel(
    const float* __restrict__ b1, const float* __restrict__ b2,
    float* __restrict__ out)
{
    extern __shared__ __half smem[];
    __half* hs = smem;                       // [128][HS_STRIDE]
    __half* ws = smem + 128 * HS_STRIDE;     // [256][WS_STRIDE]

    int tid  = threadIdx.x;
    int row0 = blockIdx.x * 128;             // 800 row tiles, never straddle b (25600%128==0)
    int bidx = row0 / (T_ * U_);

    // ---- Phase 1: fill hs[128][512] = tanh(pe + pd + b1), fp16 ----
    for (int i = tid; i < 128 * (INNER_ / 2); i += 512) {
        int r  = i >> 8;                 // 256 half2 per row
        int kk = (i & 255) << 1;
        int grow = row0 + r;
        int bt   = grow >> 6;            // (b*T + t)
        int pdr  = bidx * U_ + (r & 63); // b*U + u
        float2 pe = *(const float2*)(g_Penc + bt  * INNER_ + kk);
        float2 pd = *(const float2*)(g_Pdec + pdr * INNER_ + kk);
        float2 bb = *(const float2*)(b1 + kk);
        float t0 = tanh_fast(pe.x + pd.x + bb.x);
        float t1 = tanh_fast(pe.y + pd.y + bb.y);
        *(__half2*)(hs + r * HS_STRIDE + kk) = __floats2half2_rn(t0, t1);
    }

    int lane = tid & 31, warp = tid >> 5;
    int wm = warp & 3;          // 4 row groups of 32
    int wn = warp >> 2;         // 4 vocab groups of 64
    int arow = wm * 32 + (lane >> 2);
    int acb  = (lane & 3) * 2;
    int bnb  = wn * 64 + (lane >> 2);

    for (int vt = 0; vt < VOCAB_ / 256; ++vt) {
        float acc[2][8][4];
        #pragma unroll
        for (int mi = 0; mi < 2; mi++)
            #pragma unroll
            for (int ni = 0; ni < 8; ni++)
                #pragma unroll
                for (int q = 0; q < 4; q++) acc[mi][ni][q] = 0.f;

        for (int k0 = 0; k0 < INNER_; k0 += 64) {
            __syncthreads();
            // load W2 tile: ws[256][64]  (coalesced 128B rows)
            for (int i = tid; i < 256 * 32; i += 512) {
                int n  = i >> 5;
                int kk = (i & 31) << 1;
                *(uint32_t*)(ws + n * WS_STRIDE + kk) =
                    *(const uint32_t*)(g_W2h + (vt * 256 + n) * INNER_ + k0 + kk);
            }
            __syncthreads();

            #pragma unroll
            for (int ks = 0; ks < 64; ks += 16) {
                int kx = k0 + ks + acb;
                uint32_t a[2][4];
                #pragma unroll
                for (int mi = 0; mi < 2; mi++) {
                    const __half* base  = hs + (arow + mi * 16) * HS_STRIDE;
                    const __half* base8 = base + 8 * HS_STRIDE;
                    a[mi][0] = *(const uint32_t*)(base  + kx);
                    a[mi][1] = *(const uint32_t*)(base8 + kx);
                    a[mi][2] = *(const uint32_t*)(base  + kx + 8);
                    a[mi][3] = *(const uint32_t*)(base8 + kx + 8);
                }
                uint32_t bf[8][2];
                #pragma unroll
                for (int ni = 0; ni < 8; ni++) {
                    const __half* wb = ws + (bnb + ni * 8) * WS_STRIDE + ks + acb;
                    bf[ni][0] = *(const uint32_t*)(wb);
                    bf[ni][1] = *(const uint32_t*)(wb + 8);
                }
                #pragma unroll
                for (int mi = 0; mi < 2; mi++)
                    #pragma unroll
                    for (int ni = 0; ni < 8; ni++)
                        mma16816(acc[mi][ni], a[mi], bf[ni]);
            }
        }

        // ---- Epilogue: += b2, store fp32 ----
        #pragma unroll
        for (int mi = 0; mi < 2; mi++) {
            #pragma unroll
            for (int ni = 0; ni < 8; ni++) {
                int m = row0 + wm * 32 + mi * 16 + (lane >> 2);
                int n = vt * 256 + wn * 64 + ni * 8 + (lane & 3) * 2;
                float2 bb = *(const float2*)(b2 + n);
                float2 v0 = make_float2(acc[mi][ni][0] + bb.x, acc[mi][ni][1] + bb.y);
                float2 v1 = make_float2(acc[mi][ni][2] + bb.x, acc[mi][ni][3] + bb.y);
                *(float2*)(out + (size_t)m       * VOCAB_ + n) = v0;
                *(float2*)(out + (size_t)(m + 8) * VOCAB_ + n) = v1;
            }
        }
    }
}

// ---------------------------------------------------------------------------
extern "C" void kernel_launch(void* const* d_in, const int* in_sizes, int n_in,
                              void* d_out, int out_size)
{
    const float* enc = (const float*)d_in[0];
    const float* dec = (const float*)d_in[1];
    const float* W1  = (const float*)d_in[2];
    const float* b1  = (const float*)d_in[3];
    const float* W2  = (const float*)d_in[4];
    const float* b2  = (const float*)d_in[5];
    float* out = (float*)d_out;

    cudaFuncSetAttribute(joint_kernel,
                         cudaFuncAttributeMaxDynamicSharedMemorySize, SMEM_BYTES);

    proj_kernel<<<BT_/8 + BU_/8, 256>>>(enc, dec, W1);
    w2_convert<<<(VOCAB_*INNER_)/512, 256>>>(W2);
    joint_kernel<<<BTU_/128, 512, SMEM_BYTES>>>(b1, b2, out);
}

// round 4
// speedup vs baseline: 1.6836x; 1.6836x over previous
#include <cuda_runtime.h>
#include <cuda_fp16.h>
#include <cstdint>

#define B_  4
#define T_  400
#define U_  64
#define E_  320
#define INNER_ 512
#define VOCAB_ 1024
#define BT_ (B_*T_)      // 1600
#define BU_ (B_*U_)      // 256
#define BTU_ (B_*T_*U_)  // 102400

// Scratch (no allocations allowed -> __device__ globals)
__device__ __half g_Pench[BT_*INNER_];    // 1.6 MB fp16 enc projection
__device__ __half g_Pdech[BU_*INNER_];    // 256 KB fp16 dec projection (+b1 folded)
__device__ __half g_W2h[VOCAB_*INNER_];   // 1.0 MB fp16 W2

// ===========================================================================
// Prologue GEMM: P = X @ W1_slice^T -> fp16 (b1 folded into dec projection)
// Tiles M=64, N=128, K=32; 256 thr, thread tile 4x(4+4).
// ===========================================================================
__global__ __launch_bounds__(256) void proj_kernel(
    const float* __restrict__ enc, const float* __restrict__ dec,
    const float* __restrict__ W1, const float* __restrict__ b1)
{
    __shared__ float sx[32 * 68];    // [k][m] pad 68
    __shared__ float sw[32 * 132];   // [k][n] pad 132
    int cb = blockIdx.x;
    bool isEnc = cb < 100;
    const float* X; int mt, nt, coff;
    if (isEnc) { mt = cb >> 2;         nt = cb & 3;         X = enc; coff = 0;  }
    else       { mt = (cb - 100) >> 2; nt = (cb - 100) & 3; X = dec; coff = E_; }
    int row0 = mt * 64, col0 = nt * 128;

    int tid = threadIdx.x, tx = tid & 15, ty = tid >> 4;
    float acc[4][8];
    #pragma unroll
    for (int r = 0; r < 4; r++)
        #pragma unroll
        for (int c = 0; c < 8; c++) acc[r][c] = 0.f;

    for (int k0 = 0; k0 < E_; k0 += 32) {
        __syncthreads();
        for (int i = tid; i < 64 * 32; i += 256) {
            int r = i >> 5, k = i & 31;
            sx[k * 68 + r] = X[(row0 + r) * E_ + k0 + k];
        }
        for (int i = tid; i < 128 * 32; i += 256) {
            int n = i >> 5, k = i & 31;
            sw[k * 132 + n] = W1[(col0 + n) * (2 * E_) + coff + k0 + k];
        }
        __syncthreads();
        #pragma unroll 8
        for (int k = 0; k < 32; k++) {
            float4 xv = *(const float4*)&sx[k * 68 + ty * 4];
            float4 w0 = *(const float4*)&sw[k * 132 + tx * 4];
            float4 w1 = *(const float4*)&sw[k * 132 + 64 + tx * 4];
            float xr[4] = {xv.x, xv.y, xv.z, xv.w};
            float wr[8] = {w0.x, w0.y, w0.z, w0.w, w1.x, w1.y, w1.z, w1.w};
            #pragma unroll
            for (int r = 0; r < 4; r++)
                #pragma unroll
                for (int c = 0; c < 8; c++)
                    acc[r][c] = fmaf(xr[r], wr[c], acc[r][c]);
        }
    }

    __half* P = isEnc ? g_Pench : g_Pdech;
    #pragma unroll
    for (int r = 0; r < 4; r++) {
        int gr = row0 + ty * 4 + r;
        #pragma unroll
        for (int g = 0; g < 2; g++) {
            int cbase = col0 + g * 64 + tx * 4;
            #pragma unroll
            for (int c = 0; c < 4; c += 2) {
                float v0 = acc[r][g * 4 + c], v1 = acc[r][g * 4 + c + 1];
                if (!isEnc) { v0 += b1[cbase + c]; v1 += b1[cbase + c + 1]; }
                *(__half2*)(P + gr * INNER_ + cbase + c) = __floats2half2_rn(v0, v1);
            }
        }
    }
}

// ===========================================================================
// W2 fp32 -> fp16
// ===========================================================================
__global__ __launch_bounds__(256) void w2_convert(const float* __restrict__ W2)
{
    int i = (blockIdx.x * 256 + threadIdx.x) * 2;
    float2 v = *(const float2*)(W2 + i);
    *(__half2*)(g_W2h + i) = __floats2half2_rn(v.x, v.y);
}

// ===========================================================================
// Main fused kernel (R1-validated fragment math + cp.async double buffering).
// Per CTA: M=128 rows. hs[128][512] fp16 = tanh(pe+pd). 32 W2 chunks of
// (256 vocab x 64 k), double-buffered via cp.async; epilogue per vocab tile.
// ===========================================================================
#define HS_STRIDE 520   // halves
#define WS_STRIDE 72    // halves
#define WS_HALVES (256 * WS_STRIDE)
#define SMEM_BYTES ((128 * HS_STRIDE + 2 * WS_HALVES) * (int)sizeof(__half))  // 206848

__device__ __forceinline__ uint32_t smem_u32(const void* p) {
    uint32_t a;
    asm("{ .reg .u64 t; cvta.to.shared.u64 t, %1; cvt.u32.u64 %0, t; }" : "=r"(a) : "l"(p));
    return a;
}
__device__ __forceinline__ uint32_t tanh2(uint32_t x) {
    uint32_t y; asm("tanh.approx.f16x2 %0, %1;" : "=r"(y) : "r"(x)); return y;
}
__device__ __forceinline__ void cp16(uint32_t dst, const void* src) {
    asm volatile("cp.async.cg.shared.global [%0], [%1], 16;" :: "r"(dst), "l"(src) : "memory");
}
__device__ __forceinline__ void cp_commit() {
    asm volatile("cp.async.commit_group;" ::: "memory");
}
__device__ __forceinline__ void mma16816(float* d, const uint32_t* a, const uint32_t* b) {
    asm volatile(
        "mma.sync.aligned.m16n8k16.row.col.f32.f16.f16.f32 "
        "{%0,%1,%2,%3}, {%4,%5,%6,%7}, {%8,%9}, {%0,%1,%2,%3};\n"
        : "+f"(d[0]), "+f"(d[1]), "+f"(d[2]), "+f"(d[3])
        : "r"(a[0]), "r"(a[1]), "r"(a[2]), "r"(a[3]), "r"(b[0]), "r"(b[1]));
}

// stage one chunk (vt, kc): 256 rows x 64 halves, 4x cp.async 16B per thread
__device__ __forceinline__ void stage_chunk(uint32_t ws_u32, int chunk, int tid) {
    int vt = chunk >> 3, kc = chunk & 7;
    #pragma unroll
    for (int it = 0; it < 4; it++) {
        int i = tid + it * 512;
        int n = i >> 3, c8 = i & 7;
        cp16(ws_u32 + (n * WS_STRIDE + c8 * 8) * 2,
             g_W2h + (vt * 256 + n) * INNER_ + kc * 64 + c8 * 8);
    }
    cp_commit();
}

__global__ __launch_bounds__(512, 1) void joint_kernel(
    const float* __restrict__ b2, float* __restrict__ out)
{
    extern __shared__ __half smem[];
    __half* hs  = smem;                                  // [128][HS_STRIDE]
    __half* ws0 = smem + 128 * HS_STRIDE;                // [256][WS_STRIDE]
    __half* ws1 = ws0 + WS_HALVES;

    int tid = threadIdx.x, lane = tid & 31, warp = tid >> 5;
    int row0 = blockIdx.x * 128;
    int b    = row0 / (T_ * U_);

    uint32_t ws_u32[2] = { smem_u32(ws0), smem_u32(ws1) };

    // prefetch chunk 0 (overlaps phase-1 tanh fill)
    stage_chunk(ws_u32[0], 0, tid);

    // ---- Phase 1: hs = tanh(pe + pd) fp16 ----
    {
        const uint32_t* PE = (const uint32_t*)g_Pench;
        const uint32_t* PD = (const uint32_t*)g_Pdech;
        for (int i = tid; i < 128 * 256; i += 512) {
            int r = i >> 8, j = i & 255;
            int bt = (row0 + r) >> 6;
            uint32_t pe = __ldg(&PE[bt * 256 + j]);
            uint32_t pd = __ldg(&PD[(b * U_ + (r & 63)) * 256 + j]);
            __half2 s = __hadd2(*(__half2*)&pe, *(__half2*)&pd);
            *(uint32_t*)(hs + r * HS_STRIDE + j * 2) = tanh2(*(uint32_t*)&s);
        }
    }

    int wm = warp & 3;                 // 4 row groups of 32
    int wn = warp >> 2;                // 4 vocab groups of 64
    int arow = wm * 32 + (lane >> 2);
    int acb  = (lane & 3) * 2;
    int bnb  = wn * 64 + (lane >> 2);

    float acc[2][8][4];
    #pragma unroll
    for (int mi = 0; mi < 2; mi++)
        #pragma unroll
        for (int ni = 0; ni < 8; ni++)
            #pragma unroll
            for (int q = 0; q < 4; q++) acc[mi][ni][q] = 0.f;

    for (int ch = 0; ch < 32; ch++) {
        int vt = ch >> 3, kc = ch & 7;
        __syncthreads();   // prev compute done (or phase-1 on ch==0)
        if (ch + 1 < 32) stage_chunk(ws_u32[(ch + 1) & 1], ch + 1, tid);
        if (ch + 1 < 32) asm volatile("cp.async.wait_group 1;" ::: "memory");
        else             asm volatile("cp.async.wait_group 0;" ::: "memory");
        __syncthreads();   // chunk ch visible to all

        const __half* ws = (ch & 1) ? ws1 : ws0;

        #pragma unroll
        for (int ks = 0; ks < 64; ks += 16) {
            int kx = kc * 64 + ks + acb;     // hs column (global k)
            uint32_t a[2][4];
            #pragma unroll
            for (int mi = 0; mi < 2; mi++) {
                const __half* base  = hs + (arow + mi * 16) * HS_STRIDE;
                const __half* base8 = base + 8 * HS_STRIDE;
                a[mi][0] = *(const uint32_t*)(base  + kx);
                a[mi][1] = *(const uint32_t*)(base8 + kx);
                a[mi][2] = *(const uint32_t*)(base  + kx + 8);
                a[mi][3] = *(const uint32_t*)(base8 + kx + 8);
            }
            uint32_t bf[8][2];
            #pragma unroll
            for (int ni = 0; ni < 8; ni++) {
                const __half* wb = ws + (bnb + ni * 8) * WS_STRIDE + ks + acb;
                bf[ni][0] = *(const uint32_t*)(wb);
                bf[ni][1] = *(const uint32_t*)(wb + 8);
            }
            #pragma unroll
            for (int mi = 0; mi < 2; mi++)
                #pragma unroll
                for (int ni = 0; ni < 8; ni++)
                    mma16816(acc[mi][ni], a[mi], bf[ni]);
        }

        if (kc == 7) {
            // ---- Epilogue for vt: += b2, store fp32, reset acc ----
            #pragma unroll
            for (int mi = 0; mi < 2; mi++) {
                #pragma unroll
                for (int ni = 0; ni < 8; ni++) {
                    int m = row0 + wm * 32 + mi * 16 + (lane >> 2);
                    int n = vt * 256 + wn * 64 + ni * 8 + (lane & 3) * 2;
                    float2 bb = *(const float2*)(b2 + n);
                    float2 v0 = make_float2(acc[mi][ni][0] + bb.x, acc[mi][ni][1] + bb.y);
                    float2 v1 = make_float2(acc[mi][ni][2] + bb.x, acc[mi][ni][3] + bb.y);
                    *(float2*)(out + (size_t)m       * VOCAB_ + n) = v0;
                    *(float2*)(out + (size_t)(m + 8) * VOCAB_ + n) = v1;
                    #pragma unroll
                    for (int q = 0; q < 4; q++) acc[mi][ni][q] = 0.f;
                }
            }
        }
    }
}

// ===========================================================================
extern "C" void kernel_launch(void* const* d_in, const int* in_sizes, int n_in,
                              void* d_out, int out_size)
{
    const float* enc = (const float*)d_in[0];
    const float* dec = (const float*)d_in[1];
    const float* W1  = (const float*)d_in[2];
    const float* b1  = (const float*)d_in[3];
    const float* W2  = (const float*)d_in[4];
    const float* b2  = (const float*)d_in[5];
    float* out = (float*)d_out;

    cudaFuncSetAttribute(joint_kernel,
                         cudaFuncAttributeMaxDynamicSharedMemorySize, SMEM_BYTES);

    proj_kernel<<<116, 256>>>(enc, dec, W1, b1);
    w2_convert<<<(VOCAB_*INNER_)/512, 256>>>(W2);
    joint_kernel<<<BTU_/128, 512, SMEM_BYTES>>>(b2, out);
}